// round 10
// baseline (speedup 1.0000x reference)
#include <cuda_runtime.h>
#include <math.h>

// Problem constants
#define BATCH   4
#define CHANS   64
#define NBC     256                 // BATCH * CHANS
#define SPATIAL 524288              // 32*128*128 elements per (b,c)
#define SPAT4   131072              // SPATIAL / 4 (float4)
#define PARTS   4                   // partial blocks per bc
#define NBLK    1024                // single co-resident wave (<= 1184 capacity)
#define CHUNK4  32768               // float4 per block (512 KiB)
#define ITERS   128                 // CHUNK4 / 256 threads
#define REDR    4                   // C // R = 64/16

// Deterministic scratch (no device allocation allowed)
__device__ float g_part_s [NBLK];
__device__ float g_part_ss[NBLK];
__device__ float g_gate   [NBC];
__device__ unsigned int g_done;     // zero-init; reset by the last block each call

// ---------------------------------------------------------------------------
// Kernel 1: flat 1024-block single wave; block bid reduces the contiguous
// chunk x[bid*CHUNK4 .. +CHUNK4). Since PARTS*CHUNK4 == SPAT4, chunk bid
// belongs to bc = bid/4. SE MLP fused into the last-finishing block.
// All blocks co-resident -> zero wave transitions, balanced finish.
// ---------------------------------------------------------------------------
__global__ __launch_bounds__(256) void cca_reduce_se_kernel(
    const float4* __restrict__ x,
    const float*  __restrict__ w1, const float* __restrict__ b1,
    const float*  __restrict__ w2, const float* __restrict__ b2)
{
    const int bid = blockIdx.x;       // 0..NBLK-1
    const int tid = threadIdx.x;

    const float4* p = x + (size_t)bid * CHUNK4;

    float s = 0.f, ss = 0.f;
    #pragma unroll 16
    for (int k = 0; k < ITERS; ++k) {
        float4 v = p[k * 256 + tid];
        s  += v.x + v.y + v.z + v.w;
        ss += v.x * v.x + v.y * v.y + v.z * v.z + v.w * v.w;
    }

    // warp reduce
    #pragma unroll
    for (int o = 16; o > 0; o >>= 1) {
        s  += __shfl_xor_sync(0xffffffffu, s,  o);
        ss += __shfl_xor_sync(0xffffffffu, ss, o);
    }

    __shared__ float sh_s[8], sh_ss[8];
    __shared__ bool  sh_last;
    const int w = tid >> 5;
    if ((tid & 31) == 0) { sh_s[w] = s; sh_ss[w] = ss; }
    __syncthreads();

    if (tid == 0) {
        float ts = 0.f, tss = 0.f;
        #pragma unroll
        for (int i = 0; i < 8; ++i) { ts += sh_s[i]; tss += sh_ss[i]; }
        g_part_s [bid] = ts;
        g_part_ss[bid] = tss;
        __threadfence();                               // publish partials
        unsigned int prev = atomicAdd(&g_done, 1u);
        sh_last = (prev == NBLK - 1u);
    }
    // Let the dependent grid begin launching; the SE tail overlaps it.
    cudaTriggerProgrammaticLaunchCompletion();
    __syncthreads();
    if (!sh_last) return;

    // ---- Last block: finish reduction + SE MLP (thread t = bc index) ----
    __threadfence();                                   // acquire partials
    const int t = tid;

    float fs = 0.f, fss = 0.f;
    #pragma unroll
    for (int i = 0; i < PARTS; ++i) {
        fs  += g_part_s [t * PARTS + i];
        fss += g_part_ss[t * PARTS + i];
    }
    const float invN = 1.0f / (float)SPATIAL;
    const float mean = fs * invN;
    const float var  = fmaxf(fss * invN - mean * mean, 0.f);
    const float stdv = sqrtf(var);

    __shared__ float y[NBC];
    y[t] = stdv + mean;
    __syncthreads();

    __shared__ float h[BATCH * REDR];
    if (t < BATCH * REDR) {
        const int b = t / REDR;
        const int r = t % REDR;
        float acc = b1[r];
        #pragma unroll
        for (int c = 0; c < CHANS; ++c)
            acc += w1[r * CHANS + c] * y[b * CHANS + c];
        h[t] = fmaxf(acc, 0.f);
    }
    __syncthreads();

    const int b = t / CHANS;
    const int c = t % CHANS;
    float acc = b2[c];
    #pragma unroll
    for (int r = 0; r < REDR; ++r)
        acc += w2[c * REDR + r] * h[b * REDR + r];
    g_gate[t] = 1.0f / (1.0f + expf(-acc));

    if (t == 0) g_done = 0;                            // reset for next replay
    __threadfence();                                   // publish gate + reset
}

// ---------------------------------------------------------------------------
// Kernel 2: out = x * g[bc]. PDL secondary, flat 1024-block single wave;
// block bid owns the same contiguous chunk as reduce block bid (bc = bid/4).
// All CTAs placed during kernel 1's tail, start streaming the moment the
// gate is visible. Zero wave transitions (was 27.7 waves).
// ---------------------------------------------------------------------------
__global__ __launch_bounds__(256) void cca_scale_kernel(const float4* __restrict__ x,
                                                        float4* __restrict__ out) {
    cudaGridDependencySynchronize();                   // wait: gate now visible

    const int bid = blockIdx.x;
    const int tid = threadIdx.x;
    const float g = g_gate[bid >> 2];                  // bc = bid / PARTS

    const float4* px = x   + (size_t)bid * CHUNK4;
    float4*       po = out + (size_t)bid * CHUNK4;

    #pragma unroll 8
    for (int k = 0; k < ITERS; ++k) {
        const int i = k * 256 + tid;
        float4 v = px[i];
        v.x *= g; v.y *= g; v.z *= g; v.w *= g;
        po[i] = v;
    }
}

// ---------------------------------------------------------------------------
extern "C" void kernel_launch(void* const* d_in, const int* in_sizes, int n_in,
                              void* d_out, int out_size) {
    const float* x  = (const float*)d_in[0];   // [4,64,32,128,128]
    const float* w1 = (const float*)d_in[1];   // [4,64]
    const float* b1 = (const float*)d_in[2];   // [4]
    const float* w2 = (const float*)d_in[3];   // [64,4]
    const float* b2 = (const float*)d_in[4];   // [64]
    float* out = (float*)d_out;

    cca_reduce_se_kernel<<<NBLK, 256>>>((const float4*)x, w1, b1, w2, b2);

    // Scale kernel with programmatic dependent launch (overlap launch latency).
    cudaLaunchConfig_t cfg = {};
    cfg.gridDim  = dim3(NBLK);
    cfg.blockDim = dim3(256);
    cfg.dynamicSmemBytes = 0;
    cfg.stream = 0;                                    // same (captured) stream
    cudaLaunchAttribute attrs[1];
    attrs[0].id = cudaLaunchAttributeProgrammaticStreamSerialization;
    attrs[0].val.programmaticStreamSerializationAllowed = 1;
    cfg.attrs = attrs;
    cfg.numAttrs = 1;
    cudaLaunchKernelEx(&cfg, cca_scale_kernel, (const float4*)x, (float4*)out);
}

// round 11
// speedup vs baseline: 1.0554x; 1.0554x over previous
#include <cuda_runtime.h>
#include <math.h>

// Problem constants
#define BATCH   4
#define CHANS   64
#define NBC     256                 // BATCH * CHANS
#define SPATIAL 524288              // 32*128*128 elements per (b,c)
#define SPAT4   131072              // SPATIAL / 4 (float4)
#define PARTS   8                   // reduction blocks per (b,c)
#define REDR    4                   // C // R = 64/16
#define NRED    (NBC * PARTS)       // 2048 reduce blocks

// Scale kernel shape: 8192 blocks x 256 thr x 16 float4 = full tensor.
#define SBLK    8192
#define SBPC    32                  // scale blocks per bc (8192 / 256)
#define SCHUNK4 4096                // float4 per scale block
#define SITER   16                  // SCHUNK4 / 256

// Deterministic scratch (no device allocation allowed)
__device__ float g_part_s [NRED];
__device__ float g_part_ss[NRED];
__device__ float g_gate   [NBC];
__device__ unsigned int g_done;     // zero-init; reset by the last block each call

// ---------------------------------------------------------------------------
// Kernel 1 (R8 config, best measured): per-(b,c) partial sum / sum-of-squares,
// SE MLP fused into the last-finishing block. grid = (PARTS, NBC) = 2048
// blocks -> 1.73 waves, 86.4% DRAM measured.
// ---------------------------------------------------------------------------
__global__ __launch_bounds__(256) void cca_reduce_se_kernel(
    const float4* __restrict__ x,
    const float*  __restrict__ w1, const float* __restrict__ b1,
    const float*  __restrict__ w2, const float* __restrict__ b2)
{
    const int part = blockIdx.x;      // 0..PARTS-1
    const int bc   = blockIdx.y;      // 0..NBC-1
    const int tid  = threadIdx.x;

    const float4* p = x + (size_t)bc * SPAT4 + (size_t)part * (SPAT4 / PARTS);

    float s = 0.f, ss = 0.f;
    #pragma unroll 16
    for (int k = 0; k < 64; ++k) {
        float4 v = p[tid + k * 256];
        s  += v.x + v.y + v.z + v.w;
        ss += v.x * v.x + v.y * v.y + v.z * v.z + v.w * v.w;
    }

    // warp reduce
    #pragma unroll
    for (int o = 16; o > 0; o >>= 1) {
        s  += __shfl_xor_sync(0xffffffffu, s,  o);
        ss += __shfl_xor_sync(0xffffffffu, ss, o);
    }

    __shared__ float sh_s[8], sh_ss[8];
    __shared__ bool  sh_last;
    const int w = tid >> 5;
    if ((tid & 31) == 0) { sh_s[w] = s; sh_ss[w] = ss; }
    __syncthreads();

    if (tid == 0) {
        float ts = 0.f, tss = 0.f;
        #pragma unroll
        for (int i = 0; i < 8; ++i) { ts += sh_s[i]; tss += sh_ss[i]; }
        g_part_s [bc * PARTS + part] = ts;
        g_part_ss[bc * PARTS + part] = tss;
        __threadfence();                               // publish partials
        unsigned int prev = atomicAdd(&g_done, 1u);
        sh_last = (prev == NRED - 1u);
    }
    // Allow the dependent grid to begin launching; SE tail overlaps it.
    cudaTriggerProgrammaticLaunchCompletion();
    __syncthreads();
    if (!sh_last) return;

    // ---- Last block: finish reduction + SE MLP (thread t = bc index) ----
    __threadfence();                                   // acquire partials
    const int t = tid;

    float fs = 0.f, fss = 0.f;
    #pragma unroll
    for (int i = 0; i < PARTS; ++i) {
        fs  += g_part_s [t * PARTS + i];
        fss += g_part_ss[t * PARTS + i];
    }
    const float invN = 1.0f / (float)SPATIAL;
    const float mean = fs * invN;
    const float var  = fmaxf(fss * invN - mean * mean, 0.f);
    const float stdv = sqrtf(var);

    __shared__ float y[NBC];
    y[t] = stdv + mean;
    __syncthreads();

    __shared__ float h[BATCH * REDR];
    if (t < BATCH * REDR) {
        const int b = t / REDR;
        const int r = t % REDR;
        float acc = b1[r];
        #pragma unroll
        for (int c = 0; c < CHANS; ++c)
            acc += w1[r * CHANS + c] * y[b * CHANS + c];
        h[t] = fmaxf(acc, 0.f);
    }
    __syncthreads();

    const int b = t / CHANS;
    const int c = t % CHANS;
    float acc = b2[c];
    #pragma unroll
    for (int r = 0; r < REDR; ++r)
        acc += w2[c * REDR + r] * h[b * REDR + r];
    g_gate[t] = 1.0f / (1.0f + expf(-acc));

    if (t == 0) g_done = 0;                            // reset for next replay
    __threadfence();                                   // publish gate + reset
}

// ---------------------------------------------------------------------------
// Kernel 2: out = x * g[bc]. PDL secondary, sync at top (R8 semantics).
// 8192 blocks (~7 waves) x 16 float4/thread: multi-wave backfill absorbs
// cross-CTA spread (R10 lesson), deeper per-thread MLP hides DRAM latency,
// 4x fewer block ramps than the 32768-block layout.
// ---------------------------------------------------------------------------
__global__ __launch_bounds__(256) void cca_scale_kernel(const float4* __restrict__ x,
                                                        float4* __restrict__ out) {
    cudaGridDependencySynchronize();                   // wait: gate now visible

    const int bid = blockIdx.x;                        // 0..SBLK-1
    const int tid = threadIdx.x;
    const float g = g_gate[bid / SBPC];                // bc = bid / 32

    const float4* px = x   + (size_t)bid * SCHUNK4;
    float4*       po = out + (size_t)bid * SCHUNK4;

    #pragma unroll
    for (int k = 0; k < SITER; ++k) {
        const int i = k * 256 + tid;
        float4 v = px[i];
        v.x *= g; v.y *= g; v.z *= g; v.w *= g;
        po[i] = v;
    }
}

// ---------------------------------------------------------------------------
extern "C" void kernel_launch(void* const* d_in, const int* in_sizes, int n_in,
                              void* d_out, int out_size) {
    const float* x  = (const float*)d_in[0];   // [4,64,32,128,128]
    const float* w1 = (const float*)d_in[1];   // [4,64]
    const float* b1 = (const float*)d_in[2];   // [4]
    const float* w2 = (const float*)d_in[3];   // [64,4]
    const float* b2 = (const float*)d_in[4];   // [64]
    float* out = (float*)d_out;

    cca_reduce_se_kernel<<<dim3(PARTS, NBC), 256>>>((const float4*)x, w1, b1, w2, b2);

    // Scale kernel with programmatic dependent launch (overlap launch latency).
    cudaLaunchConfig_t cfg = {};
    cfg.gridDim  = dim3(SBLK);
    cfg.blockDim = dim3(256);
    cfg.dynamicSmemBytes = 0;
    cfg.stream = 0;                                    // same (captured) stream
    cudaLaunchAttribute attrs[1];
    attrs[0].id = cudaLaunchAttributeProgrammaticStreamSerialization;
    attrs[0].val.programmaticStreamSerializationAllowed = 1;
    cfg.attrs = attrs;
    cfg.numAttrs = 1;
    cudaLaunchKernelEx(&cfg, cca_scale_kernel, (const float4*)x, (float4*)out);
}

// round 12
// speedup vs baseline: 1.0644x; 1.0086x over previous
#include <cuda_runtime.h>
#include <math.h>

// Problem constants
#define BATCH   4
#define CHANS   64
#define NBC     256                 // BATCH * CHANS
#define SPATIAL 524288              // 32*128*128 elements per (b,c)
#define SPAT4   131072              // SPATIAL / 4 (float4)
#define PARTS   16                  // reduction blocks per (b,c)  (finer grain)
#define RITER   32                  // (SPAT4/PARTS)/256 float4 per thread
#define REDR    4                   // C // R = 64/16
#define NRED    (NBC * PARTS)       // 4096 reduce blocks

// Deterministic scratch (no device allocation allowed)
__device__ float g_part_s [NRED];
__device__ float g_part_ss[NRED];
__device__ float g_gate   [NBC];
__device__ unsigned int g_done;     // zero-init; reset by the last block each call

// ---------------------------------------------------------------------------
// Kernel 1: per-(b,c) partial sum / sum-of-squares, SE MLP fused into the
// last-finishing block. grid = (PARTS, NBC) = 4096 blocks (~3.5 waves):
// finer granularity -> later blocks backfill early-finishing SMs (R10/R11
// lesson: DRAM% rises monotonically with block count on this chip).
// ---------------------------------------------------------------------------
__global__ __launch_bounds__(256) void cca_reduce_se_kernel(
    const float4* __restrict__ x,
    const float*  __restrict__ w1, const float* __restrict__ b1,
    const float*  __restrict__ w2, const float* __restrict__ b2)
{
    const int part = blockIdx.x;      // 0..PARTS-1
    const int bc   = blockIdx.y;      // 0..NBC-1
    const int tid  = threadIdx.x;

    const float4* p = x + (size_t)bc * SPAT4 + (size_t)part * (SPAT4 / PARTS);

    float s = 0.f, ss = 0.f;
    #pragma unroll 16
    for (int k = 0; k < RITER; ++k) {
        float4 v = p[tid + k * 256];
        s  += v.x + v.y + v.z + v.w;
        ss += v.x * v.x + v.y * v.y + v.z * v.z + v.w * v.w;
    }

    // warp reduce
    #pragma unroll
    for (int o = 16; o > 0; o >>= 1) {
        s  += __shfl_xor_sync(0xffffffffu, s,  o);
        ss += __shfl_xor_sync(0xffffffffu, ss, o);
    }

    __shared__ float sh_s[8], sh_ss[8];
    __shared__ bool  sh_last;
    const int w = tid >> 5;
    if ((tid & 31) == 0) { sh_s[w] = s; sh_ss[w] = ss; }
    __syncthreads();

    if (tid == 0) {
        float ts = 0.f, tss = 0.f;
        #pragma unroll
        for (int i = 0; i < 8; ++i) { ts += sh_s[i]; tss += sh_ss[i]; }
        g_part_s [bc * PARTS + part] = ts;
        g_part_ss[bc * PARTS + part] = tss;
        __threadfence();                               // publish partials
        unsigned int prev = atomicAdd(&g_done, 1u);
        sh_last = (prev == NRED - 1u);
    }
    // Allow the dependent grid to begin launching; SE tail overlaps it.
    cudaTriggerProgrammaticLaunchCompletion();
    __syncthreads();
    if (!sh_last) return;

    // ---- Last block: finish reduction + SE MLP (thread t = bc index) ----
    __threadfence();                                   // acquire partials
    const int t = tid;

    float fs = 0.f, fss = 0.f;
    #pragma unroll
    for (int i = 0; i < PARTS; ++i) {
        fs  += g_part_s [t * PARTS + i];
        fss += g_part_ss[t * PARTS + i];
    }
    const float invN = 1.0f / (float)SPATIAL;
    const float mean = fs * invN;
    const float var  = fmaxf(fss * invN - mean * mean, 0.f);
    const float stdv = sqrtf(var);

    __shared__ float y[NBC];
    y[t] = stdv + mean;
    __syncthreads();

    __shared__ float h[BATCH * REDR];
    if (t < BATCH * REDR) {
        const int b = t / REDR;
        const int r = t % REDR;
        float acc = b1[r];
        #pragma unroll
        for (int c = 0; c < CHANS; ++c)
            acc += w1[r * CHANS + c] * y[b * CHANS + c];
        h[t] = fmaxf(acc, 0.f);
    }
    __syncthreads();

    const int b = t / CHANS;
    const int c = t % CHANS;
    float acc = b2[c];
    #pragma unroll
    for (int r = 0; r < REDR; ++r)
        acc += w2[c * REDR + r] * h[b * REDR + r];
    g_gate[t] = 1.0f / (1.0f + expf(-acc));

    if (t == 0) g_done = 0;                            // reset for next replay
    __threadfence();                                   // publish gate + reset
}

// ---------------------------------------------------------------------------
// Kernel 2: out = x * g[bc]. EXACT R8 best-measured shape: grid (128, NBC)
// = 32768 blocks, 4 float4/thread, PDL with sync at top. Finest-grain
// streaming layout -- measured 85.0-85.8% DRAM, 149.9-151.2 us.
// ---------------------------------------------------------------------------
__global__ __launch_bounds__(256) void cca_scale_kernel(const float4* __restrict__ x,
                                                        float4* __restrict__ out) {
    cudaGridDependencySynchronize();                   // wait: gate now visible

    const int bc = blockIdx.y;
    const float g = g_gate[bc];
    const size_t base = (size_t)bc * SPAT4;
    const int idx = blockIdx.x * 256 + threadIdx.x;    // 0..32767

    #pragma unroll
    for (int k = 0; k < 4; ++k) {
        const size_t i = base + idx + (size_t)k * (128 * 256);
        float4 v = x[i];
        v.x *= g; v.y *= g; v.z *= g; v.w *= g;
        out[i] = v;
    }
}

// ---------------------------------------------------------------------------
extern "C" void kernel_launch(void* const* d_in, const int* in_sizes, int n_in,
                              void* d_out, int out_size) {
    const float* x  = (const float*)d_in[0];   // [4,64,32,128,128]
    const float* w1 = (const float*)d_in[1];   // [4,64]
    const float* b1 = (const float*)d_in[2];   // [4]
    const float* w2 = (const float*)d_in[3];   // [64,4]
    const float* b2 = (const float*)d_in[4];   // [64]
    float* out = (float*)d_out;

    cca_reduce_se_kernel<<<dim3(PARTS, NBC), 256>>>((const float4*)x, w1, b1, w2, b2);

    // Scale kernel with programmatic dependent launch (overlap launch latency).
    cudaLaunchConfig_t cfg = {};
    cfg.gridDim  = dim3(128, NBC);
    cfg.blockDim = dim3(256);
    cfg.dynamicSmemBytes = 0;
    cfg.stream = 0;                                    // same (captured) stream
    cudaLaunchAttribute attrs[1];
    attrs[0].id = cudaLaunchAttributeProgrammaticStreamSerialization;
    attrs[0].val.programmaticStreamSerializationAllowed = 1;
    cfg.attrs = attrs;
    cfg.numAttrs = 1;
    cudaLaunchKernelEx(&cfg, cca_scale_kernel, (const float4*)x, (float4*)out);
}

// round 13
// speedup vs baseline: 1.0706x; 1.0058x over previous
#include <cuda_runtime.h>
#include <math.h>

// Problem constants
#define BATCH   4
#define CHANS   64
#define NBC     256                 // BATCH * CHANS
#define SPATIAL 524288              // 32*128*128 elements per (b,c)
#define SPAT4   131072              // SPATIAL / 4 (float4)
#define PARTS   8                   // reduction blocks per (b,c) (R8 best)
#define REDR    4                   // C // R = 64/16
#define NRED    (NBC * PARTS)       // 2048 reduce blocks

// Deterministic scratch (no device allocation allowed)
__device__ float g_part_s [NRED];
__device__ float g_part_ss[NRED];
__device__ float g_gate   [NBC];
__device__ unsigned int g_done;     // zero-init; reset by the last block each call

// ---------------------------------------------------------------------------
// Kernel 1: per-(b,c) partial sum / sum-of-squares, SE MLP fused into the
// last-finishing block. grid = (PARTS, NBC) = 2048 blocks.
// PDL trigger ordering (race fix): non-last blocks fire the trigger after
// publishing their partial; the LAST block fires it only AFTER g_gate is
// published. cudaGridDependencySynchronize() in the secondary returns when
// all primary CTAs have triggered/exited -> gate is provably visible.
// ---------------------------------------------------------------------------
__global__ __launch_bounds__(256) void cca_reduce_se_kernel(
    const float4* __restrict__ x,
    const float*  __restrict__ w1, const float* __restrict__ b1,
    const float*  __restrict__ w2, const float* __restrict__ b2)
{
    const int part = blockIdx.x;      // 0..PARTS-1
    const int bc   = blockIdx.y;      // 0..NBC-1
    const int tid  = threadIdx.x;

    const float4* p = x + (size_t)bc * SPAT4 + (size_t)part * (SPAT4 / PARTS);

    float s = 0.f, ss = 0.f;
    #pragma unroll 16
    for (int k = 0; k < 64; ++k) {
        float4 v = p[tid + k * 256];
        s  += v.x + v.y + v.z + v.w;
        ss += v.x * v.x + v.y * v.y + v.z * v.z + v.w * v.w;
    }

    // warp reduce
    #pragma unroll
    for (int o = 16; o > 0; o >>= 1) {
        s  += __shfl_xor_sync(0xffffffffu, s,  o);
        ss += __shfl_xor_sync(0xffffffffu, ss, o);
    }

    __shared__ float sh_s[8], sh_ss[8];
    __shared__ bool  sh_last;
    const int w = tid >> 5;
    if ((tid & 31) == 0) { sh_s[w] = s; sh_ss[w] = ss; }
    __syncthreads();

    if (tid == 0) {
        float ts = 0.f, tss = 0.f;
        #pragma unroll
        for (int i = 0; i < 8; ++i) { ts += sh_s[i]; tss += sh_ss[i]; }
        g_part_s [bc * PARTS + part] = ts;
        g_part_ss[bc * PARTS + part] = tss;
        __threadfence();                               // publish partials
        unsigned int prev = atomicAdd(&g_done, 1u);
        sh_last = (prev == NRED - 1u);
    }
    __syncthreads();
    if (!sh_last) {
        // Partials published; safe for this CTA to count toward the PDL
        // dependency. Secondary still can't pass its sync until the last
        // block (below) also triggers -- after the gate is written.
        cudaTriggerProgrammaticLaunchCompletion();
        return;
    }

    // ---- Last block: finish reduction + SE MLP (thread t = bc index) ----
    __threadfence();                                   // acquire partials
    const int t = tid;

    float fs = 0.f, fss = 0.f;
    #pragma unroll
    for (int i = 0; i < PARTS; ++i) {
        fs  += g_part_s [t * PARTS + i];
        fss += g_part_ss[t * PARTS + i];
    }
    const float invN = 1.0f / (float)SPATIAL;
    const float mean = fs * invN;
    const float var  = fmaxf(fss * invN - mean * mean, 0.f);
    const float stdv = sqrtf(var);

    __shared__ float y[NBC];
    y[t] = stdv + mean;
    __syncthreads();

    __shared__ float h[BATCH * REDR];
    if (t < BATCH * REDR) {
        const int b = t / REDR;
        const int r = t % REDR;
        float acc = b1[r];
        #pragma unroll
        for (int c = 0; c < CHANS; ++c)
            acc += w1[r * CHANS + c] * y[b * CHANS + c];
        h[t] = fmaxf(acc, 0.f);
    }
    __syncthreads();

    const int b = t / CHANS;
    const int c = t % CHANS;
    float acc = b2[c];
    #pragma unroll
    for (int r = 0; r < REDR; ++r)
        acc += w2[c * REDR + r] * h[b * REDR + r];
    g_gate[t] = 1.0f / (1.0f + expf(-acc));

    if (t == 0) g_done = 0;                            // reset for next replay
    __threadfence();                                   // publish gate + reset
    __syncthreads();                                   // all gate writes done
    cudaTriggerProgrammaticLaunchCompletion();         // NOW release secondary
}

// ---------------------------------------------------------------------------
// Kernel 2: out = x * g[bc]. PDL secondary, sync at top. Finest granularity
// yet: grid (256, NBC) = 65536 blocks, 2 float4/thread (granularity trend:
// 1024 blk 77.7% -> 8192 blk 82.7% -> 32768 blk 85.5% DRAM).
// ---------------------------------------------------------------------------
__global__ __launch_bounds__(256) void cca_scale_kernel(const float4* __restrict__ x,
                                                        float4* __restrict__ out) {
    cudaGridDependencySynchronize();                   // gate provably visible

    const int bc = blockIdx.y;
    const float g = g_gate[bc];
    const size_t base = (size_t)bc * SPAT4;
    const int idx = blockIdx.x * 256 + threadIdx.x;    // 0..65535

    #pragma unroll
    for (int k = 0; k < 2; ++k) {
        const size_t i = base + idx + (size_t)k * (256 * 256);
        float4 v = x[i];
        v.x *= g; v.y *= g; v.z *= g; v.w *= g;
        out[i] = v;
    }
}

// ---------------------------------------------------------------------------
extern "C" void kernel_launch(void* const* d_in, const int* in_sizes, int n_in,
                              void* d_out, int out_size) {
    const float* x  = (const float*)d_in[0];   // [4,64,32,128,128]
    const float* w1 = (const float*)d_in[1];   // [4,64]
    const float* b1 = (const float*)d_in[2];   // [4]
    const float* w2 = (const float*)d_in[3];   // [64,4]
    const float* b2 = (const float*)d_in[4];   // [64]
    float* out = (float*)d_out;

    cca_reduce_se_kernel<<<dim3(PARTS, NBC), 256>>>((const float4*)x, w1, b1, w2, b2);

    // Scale kernel with programmatic dependent launch (overlap launch latency).
    cudaLaunchConfig_t cfg = {};
    cfg.gridDim  = dim3(256, NBC);
    cfg.blockDim = dim3(256);
    cfg.dynamicSmemBytes = 0;
    cfg.stream = 0;                                    // same (captured) stream
    cudaLaunchAttribute attrs[1];
    attrs[0].id = cudaLaunchAttributeProgrammaticStreamSerialization;
    attrs[0].val.programmaticStreamSerializationAllowed = 1;
    cfg.attrs = attrs;
    cfg.numAttrs = 1;
    cudaLaunchKernelEx(&cfg, cca_scale_kernel, (const float4*)x, (float4*)out);
}